// round 2
// baseline (speedup 1.0000x reference)
#include <cuda_runtime.h>

#define NN 50000
#define NE 800000
#define KD 256
#define HD 256
#define LD 128

// ---------------- scratch (device globals: allocation-free) ----------------
__device__ float g_h1[(size_t)NN * HD];
__device__ float g_h2[(size_t)NN * HD];
__device__ int   g_count[NN];
__device__ int   g_cursor[NN];
__device__ int   g_rowptr[NN + 1];
__device__ int   g_scan[NN];
__device__ int   g_bsum[64];
__device__ int   g_boff[64];
__device__ float g_sval[NE];
__device__ int   g_scol[NE];
__device__ float g_stats[4 * HD];   // [sum1, sumsq1, sum2, sumsq2]

// ---------------- CSR build ----------------
__global__ void k_zero() {
    int i = blockIdx.x * blockDim.x + threadIdx.x;
    if (i < NN) { g_count[i] = 0; g_cursor[i] = 0; }
    if (i < 4 * HD) g_stats[i] = 0.f;
}

__global__ void k_hist(const int* __restrict__ rows) {
    for (int e = blockIdx.x * blockDim.x + threadIdx.x; e < NE; e += gridDim.x * blockDim.x)
        atomicAdd(&g_count[rows[e]], 1);
}

__global__ void k_scan1() {
    __shared__ int s[1024];
    int tid = threadIdx.x;
    int i = blockIdx.x * 1024 + tid;
    int v = (i < NN) ? g_count[i] : 0;
    s[tid] = v;
    __syncthreads();
    for (int off = 1; off < 1024; off <<= 1) {
        int t = (tid >= off) ? s[tid - off] : 0;
        __syncthreads();
        s[tid] += t;
        __syncthreads();
    }
    if (i < NN) g_scan[i] = s[tid];
    if (tid == 1023) g_bsum[blockIdx.x] = s[1023];
}

__global__ void k_scan2(int nb) {
    if (threadIdx.x == 0) {
        int acc = 0;
        for (int b = 0; b < nb; b++) { g_boff[b] = acc; acc += g_bsum[b]; }
    }
}

__global__ void k_scan3() {
    int i = blockIdx.x * blockDim.x + threadIdx.x;
    if (i < NN) g_rowptr[i + 1] = g_scan[i] + g_boff[i >> 10];
    if (i == 0) g_rowptr[0] = 0;
}

__global__ void k_scatter(const int* __restrict__ rows, const int* __restrict__ cols,
                          const float* __restrict__ vals) {
    for (int e = blockIdx.x * blockDim.x + threadIdx.x; e < NE; e += gridDim.x * blockDim.x) {
        int r = rows[e];
        int p = g_rowptr[r] + atomicAdd(&g_cursor[r], 1);
        g_sval[p] = vals[e];
        g_scol[p] = cols[e];
    }
}

// ---------------- SpMM: y = A @ x + bias  (one warp per row) ----------------
__global__ void k_spmm(const float* __restrict__ x, const float* __restrict__ bias,
                       float* __restrict__ y) {
    int warp = (blockIdx.x * blockDim.x + threadIdx.x) >> 5;
    int lane = threadIdx.x & 31;
    if (warp >= NN) return;
    int s = g_rowptr[warp], e = g_rowptr[warp + 1];
    float4 a0 = make_float4(0.f, 0.f, 0.f, 0.f);
    float4 a1 = make_float4(0.f, 0.f, 0.f, 0.f);
    for (int p = s; p < e; p++) {
        float v = g_sval[p];
        int c = g_scol[p];
        const float4* xr = (const float4*)(x + (size_t)c * HD);
        float4 xa = xr[lane];
        float4 xb = xr[lane + 32];
        a0.x += v * xa.x; a0.y += v * xa.y; a0.z += v * xa.z; a0.w += v * xa.w;
        a1.x += v * xb.x; a1.y += v * xb.y; a1.z += v * xb.z; a1.w += v * xb.w;
    }
    const float4* bb = (const float4*)bias;
    float4 b0 = bb[lane], b1 = bb[lane + 32];
    a0.x += b0.x; a0.y += b0.y; a0.z += b0.z; a0.w += b0.w;
    a1.x += b1.x; a1.y += b1.y; a1.z += b1.z; a1.w += b1.w;
    float4* yr = (float4*)(y + (size_t)warp * HD);
    yr[lane] = a0;
    yr[lane + 32] = a1;
}

// ---------------- BatchNorm ----------------
__global__ void k_bnstat(const float* __restrict__ x, float* __restrict__ stats) {
    int f = threadIdx.x;   // 256 threads
    float s = 0.f, s2 = 0.f;
    for (int r = blockIdx.x; r < NN; r += gridDim.x) {
        float v = x[(size_t)r * HD + f];
        s += v;
        s2 += v * v;
    }
    atomicAdd(&stats[f], s);
    atomicAdd(&stats[HD + f], s2);
}

__global__ void k_bnapply(const float* __restrict__ x, const float* __restrict__ stats,
                          const float* __restrict__ g, const float* __restrict__ be,
                          float* __restrict__ y) {
    int f = threadIdx.x;
    const float invn = 1.0f / (float)NN;
    float mean = stats[f] * invn;
    float var = stats[HD + f] * invn - mean * mean;
    float sc = rsqrtf(var + 1e-5f) * g[f];
    float sh = be[f] - mean * sc;
    for (int r = blockIdx.x; r < NN; r += gridDim.x) {
        float v = x[(size_t)r * HD + f] * sc + sh;
        y[(size_t)r * HD + f] = fmaxf(v, 0.f);
    }
}

// ---------------- SGEMM: C[M, NCOLS] = A[M,256] @ B[256,NCOLS] (+bias) ----------------
// 128x128x8 block tile, 8x8 per thread (4+4 split), 256 threads.
template <int NCOLS, bool BIAS, bool GATHER>
__global__ void __launch_bounds__(256, 2)
k_sgemm(const float* __restrict__ A, const float* __restrict__ B,
        const float* __restrict__ bias, const int* __restrict__ gidx,
        float* __restrict__ C, int M) {
    __shared__ float As[8][132];
    __shared__ float Bs[8][128];

    const int K = KD;
    int tid = threadIdx.x;
    int bn = blockIdx.x, bm = blockIdx.y;
    int tx = tid & 15, ty = tid >> 4;

    float acc[8][8];
#pragma unroll
    for (int i = 0; i < 8; i++)
#pragma unroll
        for (int j = 0; j < 8; j++) acc[i][j] = 0.f;

    int aRow = tid >> 1;
    int aK = (tid & 1) * 4;
    int bRow = tid >> 5;
    int bCol = (tid & 31) * 4;

    int gRow = bm * 128 + aRow;
    int srcRow = (gRow < M) ? gRow : (M - 1);
    if (GATHER) srcRow = gidx[srcRow];

    const float* Aptr = A + (size_t)srcRow * K + aK;
    const float* Bptr = B + (size_t)bRow * NCOLS + bn * 128 + bCol;

    for (int k0 = 0; k0 < K; k0 += 8) {
        float4 av = *(const float4*)(Aptr + k0);
        float4 bv = *(const float4*)(Bptr + (size_t)k0 * NCOLS);
        As[aK + 0][aRow] = av.x;
        As[aK + 1][aRow] = av.y;
        As[aK + 2][aRow] = av.z;
        As[aK + 3][aRow] = av.w;
        *(float4*)&Bs[bRow][bCol] = bv;
        __syncthreads();
#pragma unroll
        for (int k = 0; k < 8; k++) {
            float a[8], b[8];
            *(float4*)(a)     = *(const float4*)&As[k][ty * 4];
            *(float4*)(a + 4) = *(const float4*)&As[k][64 + ty * 4];
            *(float4*)(b)     = *(const float4*)&Bs[k][tx * 4];
            *(float4*)(b + 4) = *(const float4*)&Bs[k][64 + tx * 4];
#pragma unroll
            for (int i = 0; i < 8; i++)
#pragma unroll
                for (int j = 0; j < 8; j++) acc[i][j] += a[i] * b[j];
        }
        __syncthreads();
    }

    float4 bv0 = make_float4(0.f, 0.f, 0.f, 0.f), bv1 = bv0;
    if (BIAS) {
        bv0 = *(const float4*)(bias + bn * 128 + tx * 4);
        bv1 = *(const float4*)(bias + bn * 128 + 64 + tx * 4);
    }
#pragma unroll
    for (int half = 0; half < 2; half++) {
        int rbase = half ? (64 + ty * 4) : (ty * 4);
#pragma unroll
        for (int i = 0; i < 4; i++) {
            int m = bm * 128 + rbase + i;
            if (m < M) {
                int ai = half * 4 + i;
                float4 v0 = make_float4(acc[ai][0] + bv0.x, acc[ai][1] + bv0.y,
                                        acc[ai][2] + bv0.z, acc[ai][3] + bv0.w);
                float4 v1 = make_float4(acc[ai][4] + bv1.x, acc[ai][5] + bv1.y,
                                        acc[ai][6] + bv1.z, acc[ai][7] + bv1.w);
                float* cp = C + (size_t)m * NCOLS + bn * 128;
                *(float4*)(cp + tx * 4) = v0;
                *(float4*)(cp + 64 + tx * 4) = v1;
            }
        }
    }
}

// ---------------- launch ----------------
extern "C" void kernel_launch(void* const* d_in, const int* in_sizes, int n_in,
                              void* d_out, int out_size) {
    const float* features = (const float*)d_in[0];
    const float* evals    = (const float*)d_in[1];
    const float* W1       = (const float*)d_in[2];
    const float* db1      = (const float*)d_in[3];
    const float* b1       = (const float*)d_in[4];
    const float* g1       = (const float*)d_in[5];
    const float* be1      = (const float*)d_in[6];
    const float* W2       = (const float*)d_in[7];
    const float* b2       = (const float*)d_in[8];
    const float* g2       = (const float*)d_in[9];
    const float* be2      = (const float*)d_in[10];
    const float* Wf       = (const float*)d_in[11];
    const float* bf       = (const float*)d_in[12];
    const int*   erows    = (const int*)d_in[13];
    const int*   ecols    = (const int*)d_in[14];
    const int*   idx      = (const int*)d_in[15];
    float* out = (float*)d_out;
    int Midx = in_sizes[15];

    float *h1, *h2, *stats;
    cudaGetSymbolAddress((void**)&h1, g_h1);
    cudaGetSymbolAddress((void**)&h2, g_h2);
    cudaGetSymbolAddress((void**)&stats, g_stats);

    int nb1 = (NN + 1023) / 1024;

    // CSR build (re-done every call: deterministic structure, atomic order only
    // perturbs fp sum order by ~1 ulp)
    k_zero<<<(NN + 255) / 256, 256>>>();
    k_hist<<<512, 256>>>(erows);
    k_scan1<<<nb1, 1024>>>();
    k_scan2<<<1, 32>>>(nb1);
    k_scan3<<<(NN + 255) / 256, 256>>>();
    k_scatter<<<512, 256>>>(erows, ecols, evals);

    dim3 gBig(HD / 128, (NN + 127) / 128);
    int spmmBlocks = (NN * 32 + 255) / 256;

    // layer 1
    k_sgemm<HD, true, false><<<gBig, 256>>>(features, W1, db1, nullptr, h1, NN);
    k_spmm<<<spmmBlocks, 256>>>(h1, b1, h2);
    k_bnstat<<<256, HD>>>(h2, stats);
    k_bnapply<<<512, HD>>>(h2, stats, g1, be1, h1);

    // layer 2
    k_sgemm<HD, false, false><<<gBig, 256>>>(h1, W2, nullptr, nullptr, h2, NN);
    k_spmm<<<spmmBlocks, 256>>>(h2, b2, h1);
    k_bnstat<<<256, HD>>>(h1, stats + 2 * HD);
    k_bnapply<<<512, HD>>>(h1, stats + 2 * HD, g2, be2, h2);

    // gathered head
    dim3 gHead(LD / 128, (Midx + 127) / 128);
    k_sgemm<LD, true, true><<<gHead, 256>>>(h2, Wf, bf, idx, out, Midx);
}

// round 3
// speedup vs baseline: 1.2945x; 1.2945x over previous
#include <cuda_runtime.h>

#define NN 50000
#define NE 800000
#define KD 256
#define HD 256
#define LD 128

// ---------------- scratch (device globals: allocation-free) ----------------
__device__ float g_h1[(size_t)NN * HD];
__device__ float g_h2[(size_t)NN * HD];
__device__ int   g_count[NN];
__device__ int   g_cursor[NN];
__device__ int   g_rowptr[NN + 1];
__device__ int   g_scan[NN];
__device__ int   g_bsum[64];
__device__ int   g_boff[64];
__device__ float g_sval[NE];
__device__ int   g_scol[NE];
__device__ float g_stats[4 * HD];   // [sum1, sumsq1 | sum2, sumsq2]

// ---------------- CSR build ----------------
__global__ void k_zero() {
    int i = blockIdx.x * blockDim.x + threadIdx.x;
    if (i < NN) { g_count[i] = 0; g_cursor[i] = 0; }
    if (i < 4 * HD) g_stats[i] = 0.f;
}

__global__ void k_hist(const int* __restrict__ rows) {
    for (int e = blockIdx.x * blockDim.x + threadIdx.x; e < NE; e += gridDim.x * blockDim.x)
        atomicAdd(&g_count[rows[e]], 1);
}

__global__ void k_scan1() {
    __shared__ int s[1024];
    int tid = threadIdx.x;
    int i = blockIdx.x * 1024 + tid;
    int v = (i < NN) ? g_count[i] : 0;
    s[tid] = v;
    __syncthreads();
    for (int off = 1; off < 1024; off <<= 1) {
        int t = (tid >= off) ? s[tid - off] : 0;
        __syncthreads();
        s[tid] += t;
        __syncthreads();
    }
    if (i < NN) g_scan[i] = s[tid];
    if (tid == 1023) g_bsum[blockIdx.x] = s[1023];
}

__global__ void k_scan2(int nb) {   // 64-thread inclusive scan -> exclusive offsets
    __shared__ int s[64];
    int t = threadIdx.x;
    s[t] = (t < nb) ? g_bsum[t] : 0;
    __syncthreads();
    for (int off = 1; off < 64; off <<= 1) {
        int v = (t >= off) ? s[t - off] : 0;
        __syncthreads();
        s[t] += v;
        __syncthreads();
    }
    if (t < nb) g_boff[t] = (t == 0) ? 0 : s[t - 1];
}

__global__ void k_scan3() {
    int i = blockIdx.x * blockDim.x + threadIdx.x;
    if (i < NN) g_rowptr[i + 1] = g_scan[i] + g_boff[i >> 10];
    if (i == 0) g_rowptr[0] = 0;
}

__global__ void k_scatter(const int* __restrict__ rows, const int* __restrict__ cols,
                          const float* __restrict__ vals) {
    for (int e = blockIdx.x * blockDim.x + threadIdx.x; e < NE; e += gridDim.x * blockDim.x) {
        int r = rows[e];
        int p = g_rowptr[r] + atomicAdd(&g_cursor[r], 1);
        g_sval[p] = vals[e];
        g_scol[p] = cols[e];
    }
}

// ---------------- SpMM: y = A @ x + bias, fused BN-stats epilogue ----------------
// one warp per row; 8 warps/block; NN % 8 == 0 so no partial blocks.
__global__ void k_spmm(const float* __restrict__ x, const float* __restrict__ bias,
                       float* __restrict__ y, float* __restrict__ stats) {
    __shared__ float ssum[HD];
    __shared__ float ssq[HD];
    int tid = threadIdx.x;
    ssum[tid] = 0.f;
    ssq[tid] = 0.f;
    __syncthreads();

    int warp = (blockIdx.x * blockDim.x + tid) >> 5;
    int lane = tid & 31;
    float4 a0 = make_float4(0.f, 0.f, 0.f, 0.f);
    float4 a1 = make_float4(0.f, 0.f, 0.f, 0.f);
    if (warp < NN) {
        int s = g_rowptr[warp], e = g_rowptr[warp + 1];
        for (int p = s; p < e; p++) {
            float v = g_sval[p];
            int c = g_scol[p];
            const float4* xr = (const float4*)(x + (size_t)c * HD);
            float4 xa = xr[lane];
            float4 xb = xr[lane + 32];
            a0.x += v * xa.x; a0.y += v * xa.y; a0.z += v * xa.z; a0.w += v * xa.w;
            a1.x += v * xb.x; a1.y += v * xb.y; a1.z += v * xb.z; a1.w += v * xb.w;
        }
        const float4* bb = (const float4*)bias;
        float4 b0 = bb[lane], b1 = bb[lane + 32];
        a0.x += b0.x; a0.y += b0.y; a0.z += b0.z; a0.w += b0.w;
        a1.x += b1.x; a1.y += b1.y; a1.z += b1.z; a1.w += b1.w;
        float4* yr = (float4*)(y + (size_t)warp * HD);
        yr[lane] = a0;
        yr[lane + 32] = a1;

        // per-feature partial sums into shared (lane l covers f=4l..4l+3, 128+4l..)
        int f0 = 4 * lane, f1 = 128 + 4 * lane;
        atomicAdd(&ssum[f0 + 0], a0.x); atomicAdd(&ssq[f0 + 0], a0.x * a0.x);
        atomicAdd(&ssum[f0 + 1], a0.y); atomicAdd(&ssq[f0 + 1], a0.y * a0.y);
        atomicAdd(&ssum[f0 + 2], a0.z); atomicAdd(&ssq[f0 + 2], a0.z * a0.z);
        atomicAdd(&ssum[f0 + 3], a0.w); atomicAdd(&ssq[f0 + 3], a0.w * a0.w);
        atomicAdd(&ssum[f1 + 0], a1.x); atomicAdd(&ssq[f1 + 0], a1.x * a1.x);
        atomicAdd(&ssum[f1 + 1], a1.y); atomicAdd(&ssq[f1 + 1], a1.y * a1.y);
        atomicAdd(&ssum[f1 + 2], a1.z); atomicAdd(&ssq[f1 + 2], a1.z * a1.z);
        atomicAdd(&ssum[f1 + 3], a1.w); atomicAdd(&ssq[f1 + 3], a1.w * a1.w);
    }
    __syncthreads();
    atomicAdd(&stats[tid], ssum[tid]);
    atomicAdd(&stats[HD + tid], ssq[tid]);
}

// ---------------- SGEMM: C[M, NCOLS] = act(A)[M,256] @ B[256,NCOLS] (+bias) ---------
// act(A) = relu(A*sc + sh) per K-column when BNA (BN fused into A-read).
// 128x128x8 block tile, 8x8 per thread (4+4 split), 256 threads.
template <int NCOLS, bool BIAS, bool GATHER, bool BNA>
__global__ void __launch_bounds__(256, 2)
k_sgemm(const float* __restrict__ A, const float* __restrict__ B,
        const float* __restrict__ bias, const int* __restrict__ gidx,
        const float* __restrict__ bnstats, const float* __restrict__ bng,
        const float* __restrict__ bnbe,
        float* __restrict__ C, int M) {
    __shared__ float As[8][132];
    __shared__ float Bs[8][128];
    __shared__ float s_sc[KD];
    __shared__ float s_sh[KD];

    const int K = KD;
    int tid = threadIdx.x;
    int bn = blockIdx.x, bm = blockIdx.y;
    int tx = tid & 15, ty = tid >> 4;

    if (BNA) {
        const float invn = 1.0f / (float)NN;
        float mean = bnstats[tid] * invn;
        float var = bnstats[KD + tid] * invn - mean * mean;
        float sc = rsqrtf(var + 1e-5f) * bng[tid];
        s_sc[tid] = sc;
        s_sh[tid] = bnbe[tid] - mean * sc;
    }

    float acc[8][8];
#pragma unroll
    for (int i = 0; i < 8; i++)
#pragma unroll
        for (int j = 0; j < 8; j++) acc[i][j] = 0.f;

    int aRow = tid >> 1;
    int aK = (tid & 1) * 4;
    int bRow = tid >> 5;
    int bCol = (tid & 31) * 4;

    int gRow = bm * 128 + aRow;
    int srcRow = (gRow < M) ? gRow : (M - 1);
    if (GATHER) srcRow = gidx[srcRow];

    const float* Aptr = A + (size_t)srcRow * K + aK;
    const float* Bptr = B + (size_t)bRow * NCOLS + bn * 128 + bCol;

    if (BNA) __syncthreads();   // s_sc/s_sh ready

    for (int k0 = 0; k0 < K; k0 += 8) {
        float4 av = *(const float4*)(Aptr + k0);
        float4 bv = *(const float4*)(Bptr + (size_t)k0 * NCOLS);
        if (BNA) {
            float4 sc4 = *(const float4*)&s_sc[k0 + aK];
            float4 sh4 = *(const float4*)&s_sh[k0 + aK];
            av.x = fmaxf(av.x * sc4.x + sh4.x, 0.f);
            av.y = fmaxf(av.y * sc4.y + sh4.y, 0.f);
            av.z = fmaxf(av.z * sc4.z + sh4.z, 0.f);
            av.w = fmaxf(av.w * sc4.w + sh4.w, 0.f);
        }
        As[aK + 0][aRow] = av.x;
        As[aK + 1][aRow] = av.y;
        As[aK + 2][aRow] = av.z;
        As[aK + 3][aRow] = av.w;
        *(float4*)&Bs[bRow][bCol] = bv;
        __syncthreads();
#pragma unroll
        for (int k = 0; k < 8; k++) {
            float a[8], b[8];
            *(float4*)(a)     = *(const float4*)&As[k][ty * 4];
            *(float4*)(a + 4) = *(const float4*)&As[k][64 + ty * 4];
            *(float4*)(b)     = *(const float4*)&Bs[k][tx * 4];
            *(float4*)(b + 4) = *(const float4*)&Bs[k][64 + tx * 4];
#pragma unroll
            for (int i = 0; i < 8; i++)
#pragma unroll
                for (int j = 0; j < 8; j++) acc[i][j] += a[i] * b[j];
        }
        __syncthreads();
    }

    float4 bv0 = make_float4(0.f, 0.f, 0.f, 0.f), bv1 = bv0;
    if (BIAS) {
        bv0 = *(const float4*)(bias + bn * 128 + tx * 4);
        bv1 = *(const float4*)(bias + bn * 128 + 64 + tx * 4);
    }
#pragma unroll
    for (int half = 0; half < 2; half++) {
        int rbase = half ? (64 + ty * 4) : (ty * 4);
#pragma unroll
        for (int i = 0; i < 4; i++) {
            int m = bm * 128 + rbase + i;
            if (m < M) {
                int ai = half * 4 + i;
                float4 v0 = make_float4(acc[ai][0] + bv0.x, acc[ai][1] + bv0.y,
                                        acc[ai][2] + bv0.z, acc[ai][3] + bv0.w);
                float4 v1 = make_float4(acc[ai][4] + bv1.x, acc[ai][5] + bv1.y,
                                        acc[ai][6] + bv1.z, acc[ai][7] + bv1.w);
                float* cp = C + (size_t)m * NCOLS + bn * 128;
                *(float4*)(cp + tx * 4) = v0;
                *(float4*)(cp + 64 + tx * 4) = v1;
            }
        }
    }
}

// ---------------- launch ----------------
extern "C" void kernel_launch(void* const* d_in, const int* in_sizes, int n_in,
                              void* d_out, int out_size) {
    const float* features = (const float*)d_in[0];
    const float* evals    = (const float*)d_in[1];
    const float* W1       = (const float*)d_in[2];
    const float* db1      = (const float*)d_in[3];
    const float* b1       = (const float*)d_in[4];
    const float* g1       = (const float*)d_in[5];
    const float* be1      = (const float*)d_in[6];
    const float* W2       = (const float*)d_in[7];
    const float* b2       = (const float*)d_in[8];
    const float* g2       = (const float*)d_in[9];
    const float* be2      = (const float*)d_in[10];
    const float* Wf       = (const float*)d_in[11];
    const float* bf       = (const float*)d_in[12];
    const int*   erows    = (const int*)d_in[13];
    const int*   ecols    = (const int*)d_in[14];
    const int*   idx      = (const int*)d_in[15];
    float* out = (float*)d_out;
    int Midx = in_sizes[15];

    float *h1, *h2, *stats;
    cudaGetSymbolAddress((void**)&h1, g_h1);
    cudaGetSymbolAddress((void**)&h2, g_h2);
    cudaGetSymbolAddress((void**)&stats, g_stats);

    int nb1 = (NN + 1023) / 1024;

    // CSR build (deterministic structure; atomic order only perturbs fp sums ~1 ulp)
    k_zero<<<(NN + 255) / 256, 256>>>();
    k_hist<<<512, 256>>>(erows);
    k_scan1<<<nb1, 1024>>>();
    k_scan2<<<1, 64>>>(nb1);
    k_scan3<<<(NN + 255) / 256, 256>>>();
    k_scatter<<<512, 256>>>(erows, ecols, evals);

    dim3 gBig(HD / 128, (NN + 127) / 128);
    int spmmBlocks = (NN * 32 + 255) / 256;

    // layer 1: GEMM -> SpMM(+bias, +BN stats)
    k_sgemm<HD, true, false, false><<<gBig, 256>>>(features, W1, db1, nullptr,
                                                   nullptr, nullptr, nullptr, h1, NN);
    k_spmm<<<spmmBlocks, 256>>>(h1, b1, h2, stats);

    // layer 2: GEMM with fused BN1+ReLU on A-read -> SpMM(+bias, +BN stats)
    k_sgemm<HD, false, false, true><<<gBig, 256>>>(h2, W2, nullptr, nullptr,
                                                   stats, g1, be1, h1, NN);
    k_spmm<<<spmmBlocks, 256>>>(h1, b2, h2, stats + 2 * HD);

    // head: gathered GEMM with fused BN2+ReLU on A-read
    dim3 gHead(LD / 128, (Midx + 127) / 128);
    k_sgemm<LD, true, true, true><<<gHead, 256>>>(h2, Wf, bf, idx,
                                                  stats + 2 * HD, g2, be2, out, Midx);
}

// round 6
// speedup vs baseline: 1.6445x; 1.2704x over previous
#include <cuda_runtime.h>
#include <cuda_bf16.h>
#include <cstdint>

#define NN 50000
#define NE 800000
#define KD 256
#define HD 256
#define LD 128

// ---------------- scratch (device globals: allocation-free) ----------------
__device__ float g_h1[(size_t)NN * HD];
__device__ float g_h2[(size_t)NN * HD];
__device__ int   g_count[NN];
__device__ int   g_cursor[NN];
__device__ int   g_rowptr[NN + 1];
__device__ int   g_scan[NN];
__device__ int   g_bsum[64];
__device__ int   g_boff[64];
__device__ float g_sval[NE];
__device__ int   g_scol[NE];
__device__ float g_stats[4 * HD];                 // [sum1, sumsq1 | sum2, sumsq2]
__device__ __nv_bfloat16 g_Bhi[3 * KD * HD];      // split weights, [N,K] layout
__device__ __nv_bfloat16 g_Blo[3 * KD * HD];

// ---------------- helpers ----------------
__device__ __forceinline__ uint32_t smem_u32(const void* p) {
    uint32_t a;
    asm("{ .reg .u64 t; cvta.to.shared.u64 t, %1; cvt.u32.u64 %0, t; }" : "=r"(a) : "l"(p));
    return a;
}
__device__ __forceinline__ void ldsm4(uint32_t& r0, uint32_t& r1, uint32_t& r2,
                                      uint32_t& r3, uint32_t addr) {
    asm volatile("ldmatrix.sync.aligned.m8n8.x4.shared.b16 {%0,%1,%2,%3}, [%4];"
                 : "=r"(r0), "=r"(r1), "=r"(r2), "=r"(r3) : "r"(addr));
}
__device__ __forceinline__ void mma16816(float* d, const uint32_t* a, const uint32_t* b) {
    asm volatile(
        "mma.sync.aligned.m16n8k16.row.col.f32.bf16.bf16.f32 "
        "{%0,%1,%2,%3}, {%4,%5,%6,%7}, {%8,%9}, {%0,%1,%2,%3};"
        : "+f"(d[0]), "+f"(d[1]), "+f"(d[2]), "+f"(d[3])
        : "r"(a[0]), "r"(a[1]), "r"(a[2]), "r"(a[3]), "r"(b[0]), "r"(b[1]));
}

// ---------------- CSR build ----------------
__global__ void k_zero() {
    int i = blockIdx.x * blockDim.x + threadIdx.x;
    if (i < NN) { g_count[i] = 0; g_cursor[i] = 0; }
    if (i < 4 * HD) g_stats[i] = 0.f;
}
__global__ void k_hist(const int* __restrict__ rows) {
    for (int e = blockIdx.x * blockDim.x + threadIdx.x; e < NE; e += gridDim.x * blockDim.x)
        atomicAdd(&g_count[rows[e]], 1);
}
__global__ void k_scan1() {
    __shared__ int s[1024];
    int tid = threadIdx.x;
    int i = blockIdx.x * 1024 + tid;
    int v = (i < NN) ? g_count[i] : 0;
    s[tid] = v;
    __syncthreads();
    for (int off = 1; off < 1024; off <<= 1) {
        int t = (tid >= off) ? s[tid - off] : 0;
        __syncthreads();
        s[tid] += t;
        __syncthreads();
    }
    if (i < NN) g_scan[i] = s[tid];
    if (tid == 1023) g_bsum[blockIdx.x] = s[1023];
}
__global__ void k_scan2(int nb) {
    __shared__ int s[64];
    int t = threadIdx.x;
    s[t] = (t < nb) ? g_bsum[t] : 0;
    __syncthreads();
    for (int off = 1; off < 64; off <<= 1) {
        int v = (t >= off) ? s[t - off] : 0;
        __syncthreads();
        s[t] += v;
        __syncthreads();
    }
    if (t < nb) g_boff[t] = (t == 0) ? 0 : s[t - 1];
}
__global__ void k_scan3() {
    int i = blockIdx.x * blockDim.x + threadIdx.x;
    if (i < NN) g_rowptr[i + 1] = g_scan[i] + g_boff[i >> 10];
    if (i == 0) g_rowptr[0] = 0;
}
__global__ void k_scatter(const int* __restrict__ rows, const int* __restrict__ cols,
                          const float* __restrict__ vals) {
    for (int e = blockIdx.x * blockDim.x + threadIdx.x; e < NE; e += gridDim.x * blockDim.x) {
        int r = rows[e];
        int p = g_rowptr[r] + atomicAdd(&g_cursor[r], 1);
        g_sval[p] = vals[e];
        g_scol[p] = cols[e];
    }
}

// ---------------- weight split: W[K,Ncols] fp32 -> Bhi/Blo[Ncols,K] bf16 ----------------
__global__ void k_convW(const float* __restrict__ W, __nv_bfloat16* __restrict__ bhi,
                        __nv_bfloat16* __restrict__ blo, int Ncols) {
    int i = blockIdx.x * blockDim.x + threadIdx.x;
    if (i >= Ncols * KD) return;
    int n = i >> 8, k = i & 255;
    float v = W[k * Ncols + n];
    __nv_bfloat16 h = __float2bfloat16(v);
    bhi[i] = h;
    blo[i] = __float2bfloat16(v - __bfloat162float(h));
}

// ---------------- SpMM: y = A @ x + bias, fused BN-stats epilogue ----------------
__global__ void k_spmm(const float* __restrict__ x, const float* __restrict__ bias,
                       float* __restrict__ y, float* __restrict__ stats) {
    __shared__ float ssum[HD];
    __shared__ float ssq[HD];
    int tid = threadIdx.x;
    ssum[tid] = 0.f;
    ssq[tid] = 0.f;
    __syncthreads();

    int warp = (blockIdx.x * blockDim.x + tid) >> 5;
    int lane = tid & 31;
    float4 a0 = make_float4(0.f, 0.f, 0.f, 0.f);
    float4 a1 = make_float4(0.f, 0.f, 0.f, 0.f);
    if (warp < NN) {
        int s = g_rowptr[warp], e = g_rowptr[warp + 1];
        for (int p = s; p < e; p++) {
            float v = g_sval[p];
            int c = g_scol[p];
            const float4* xr = (const float4*)(x + (size_t)c * HD);
            float4 xa = xr[lane];
            float4 xb = xr[lane + 32];
            a0.x += v * xa.x; a0.y += v * xa.y; a0.z += v * xa.z; a0.w += v * xa.w;
            a1.x += v * xb.x; a1.y += v * xb.y; a1.z += v * xb.z; a1.w += v * xb.w;
        }
        const float4* bb = (const float4*)bias;
        float4 b0 = bb[lane], b1 = bb[lane + 32];
        a0.x += b0.x; a0.y += b0.y; a0.z += b0.z; a0.w += b0.w;
        a1.x += b1.x; a1.y += b1.y; a1.z += b1.z; a1.w += b1.w;
        float4* yr = (float4*)(y + (size_t)warp * HD);
        yr[lane] = a0;
        yr[lane + 32] = a1;

        int f0 = 4 * lane, f1 = 128 + 4 * lane;
        atomicAdd(&ssum[f0 + 0], a0.x); atomicAdd(&ssq[f0 + 0], a0.x * a0.x);
        atomicAdd(&ssum[f0 + 1], a0.y); atomicAdd(&ssq[f0 + 1], a0.y * a0.y);
        atomicAdd(&ssum[f0 + 2], a0.z); atomicAdd(&ssq[f0 + 2], a0.z * a0.z);
        atomicAdd(&ssum[f0 + 3], a0.w); atomicAdd(&ssq[f0 + 3], a0.w * a0.w);
        atomicAdd(&ssum[f1 + 0], a1.x); atomicAdd(&ssq[f1 + 0], a1.x * a1.x);
        atomicAdd(&ssum[f1 + 1], a1.y); atomicAdd(&ssq[f1 + 1], a1.y * a1.y);
        atomicAdd(&ssum[f1 + 2], a1.z); atomicAdd(&ssq[f1 + 2], a1.z * a1.z);
        atomicAdd(&ssum[f1 + 3], a1.w); atomicAdd(&ssq[f1 + 3], a1.w * a1.w);
    }
    __syncthreads();
    atomicAdd(&stats[tid], ssum[tid]);
    atomicAdd(&stats[HD + tid], ssq[tid]);
}

// ---------------- HMMA GEMM: C[M,NCOLS] = act(A)[M,256] @ B^T (+bias) ----------------
// A fp32 (optionally BN+ReLU, optionally gathered) split to bf16 hi/lo in-register.
// B pre-split bf16 hi/lo [N,K]. acc fp32 via 3 chains: hi*hi + lo*hi + hi*lo.
// Block tile 128x128, warps 4(m)x2(n), warp tile 32x64, K chunk 32.
#define A_HI 0
#define A_LO 10240
#define B_HI 20480
#define B_LO 30720
#define SC_OFF 40960
#define SH_OFF 41984

template <int NCOLS, bool BIAS, bool GATHER, bool BNA>
__global__ void __launch_bounds__(256)
k_mmagemm(const float* __restrict__ A, const __nv_bfloat16* __restrict__ Bhi,
          const __nv_bfloat16* __restrict__ Blo, const float* __restrict__ bias,
          const int* __restrict__ gidx, const float* __restrict__ bnstats,
          const float* __restrict__ bng, const float* __restrict__ bnbe,
          float* __restrict__ C, int M) {
    __shared__ __align__(16) char smem[43008];
    int tid = threadIdx.x, lane = tid & 31, wid = tid >> 5;
    int bn = blockIdx.x, bm = blockIdx.y;
    int wm = wid >> 1, wn = wid & 1;

    float* s_sc = (float*)(smem + SC_OFF);
    float* s_sh = (float*)(smem + SH_OFF);
    if (BNA) {
        const float invn = 1.0f / (float)NN;
        float mean = bnstats[tid] * invn;
        float var = bnstats[KD + tid] * invn - mean * mean;
        float sc = rsqrtf(var + 1e-5f) * bng[tid];
        s_sc[tid] = sc;
        s_sh[tid] = bnbe[tid] - mean * sc;
        __syncthreads();   // FIX (R5 bug): s_sc/s_sh must be visible before first A-load uses them
    }

    // global load mapping: thread t -> row r = t>>1, 16-wide K segment (t&1)*16
    int r = tid >> 1;
    int kseg = (tid & 1) * 16;
    int gRow = bm * 128 + r;
    int srcRow = (gRow < M) ? gRow : (M - 1);
    if (GATHER) srcRow = gidx[srcRow];
    const float* Ap = A + (size_t)srcRow * KD + kseg;
    const __nv_bfloat16* Bph = Bhi + (size_t)(bn * 128 + r) * KD + kseg;
    const __nv_bfloat16* Bpl = Blo + (size_t)(bn * 128 + r) * KD + kseg;
    uint32_t st_off = (uint32_t)(r * 80 + kseg * 2);   // byte offset in padded tile

    uint32_t sb = smem_u32(smem);
    // ldmatrix lane addressing
    uint32_t aoff = (uint32_t)((wm * 32 + (lane & 15)) * 80 + ((lane >> 4) * 16));
    uint32_t boff = (uint32_t)((wn * 64 + (lane & 7) + ((lane >> 4) * 8)) * 80 +
                               (((lane >> 3) & 1) * 16));

    float acc[2][8][4];
#pragma unroll
    for (int mt = 0; mt < 2; mt++)
#pragma unroll
        for (int nt = 0; nt < 8; nt++)
#pragma unroll
            for (int q = 0; q < 4; q++) acc[mt][nt][q] = 0.f;

#pragma unroll 1
    for (int c = 0; c < 8; c++) {
        int k0 = c * 32;
        // ---- A: global fp32 -> (BN/ReLU) -> hi/lo bf16 regs ----
        float v[16];
#pragma unroll
        for (int i = 0; i < 4; i++) {
            float4 f = *(const float4*)(Ap + k0 + i * 4);
            v[i * 4 + 0] = f.x; v[i * 4 + 1] = f.y;
            v[i * 4 + 2] = f.z; v[i * 4 + 3] = f.w;
        }
        if (BNA) {
#pragma unroll
            for (int j = 0; j < 16; j++) {
                int kk = k0 + kseg + j;
                v[j] = fmaxf(v[j] * s_sc[kk] + s_sh[kk], 0.f);
            }
        }
        uint32_t ph[8], pl[8];
#pragma unroll
        for (int j = 0; j < 8; j++) {
            __nv_bfloat16 h0 = __float2bfloat16(v[2 * j]);
            __nv_bfloat16 h1 = __float2bfloat16(v[2 * j + 1]);
            __nv_bfloat16 l0 = __float2bfloat16(v[2 * j] - __bfloat162float(h0));
            __nv_bfloat16 l1 = __float2bfloat16(v[2 * j + 1] - __bfloat162float(h1));
            __nv_bfloat162 hp(h0, h1), lp(l0, l1);
            ph[j] = *(uint32_t*)&hp;
            pl[j] = *(uint32_t*)&lp;
        }
        // ---- B: pre-split bf16 ----
        uint4 bh0 = *(const uint4*)(Bph + k0);
        uint4 bh1 = *(const uint4*)(Bph + k0 + 8);
        uint4 bl0 = *(const uint4*)(Bpl + k0);
        uint4 bl1 = *(const uint4*)(Bpl + k0 + 8);

        __syncthreads();   // previous chunk's compute done
        *(uint4*)(smem + A_HI + st_off)      = make_uint4(ph[0], ph[1], ph[2], ph[3]);
        *(uint4*)(smem + A_HI + st_off + 16) = make_uint4(ph[4], ph[5], ph[6], ph[7]);
        *(uint4*)(smem + A_LO + st_off)      = make_uint4(pl[0], pl[1], pl[2], pl[3]);
        *(uint4*)(smem + A_LO + st_off + 16) = make_uint4(pl[4], pl[5], pl[6], pl[7]);
        *(uint4*)(smem + B_HI + st_off)      = bh0;
        *(uint4*)(smem + B_HI + st_off + 16) = bh1;
        *(uint4*)(smem + B_LO + st_off)      = bl0;
        *(uint4*)(smem + B_LO + st_off + 16) = bl1;
        __syncthreads();

        // ---- compute: 2 k16 steps ----
#pragma unroll
        for (int ks = 0; ks < 2; ks++) {
            uint32_t kb = ks * 32;   // 16 bf16 = 32 bytes
            uint32_t ah[2][4], al[2][4];
#pragma unroll
            for (int mt = 0; mt < 2; mt++) {
                ldsm4(ah[mt][0], ah[mt][1], ah[mt][2], ah[mt][3],
                      sb + A_HI + aoff + mt * 16 * 80 + kb);
                ldsm4(al[mt][0], al[mt][1], al[mt][2], al[mt][3],
                      sb + A_LO + aoff + mt * 16 * 80 + kb);
            }
            uint32_t bh[8][2], bl[8][2];
#pragma unroll
            for (int np = 0; np < 4; np++) {
                ldsm4(bh[2 * np][0], bh[2 * np][1], bh[2 * np + 1][0], bh[2 * np + 1][1],
                      sb + B_HI + boff + np * 16 * 80 + kb);
                ldsm4(bl[2 * np][0], bl[2 * np][1], bl[2 * np + 1][0], bl[2 * np + 1][1],
                      sb + B_LO + boff + np * 16 * 80 + kb);
            }
#pragma unroll
            for (int mt = 0; mt < 2; mt++)
#pragma unroll
                for (int nt = 0; nt < 8; nt++) {
                    mma16816(acc[mt][nt], ah[mt], bh[nt]);
                    mma16816(acc[mt][nt], al[mt], bh[nt]);
                    mma16816(acc[mt][nt], ah[mt], bl[nt]);
                }
        }
    }

    // ---- epilogue: registers -> global (+bias) ----
#pragma unroll
    for (int nt = 0; nt < 8; nt++) {
        int col = bn * 128 + wn * 64 + nt * 8 + (lane & 3) * 2;
        float bx = 0.f, by = 0.f;
        if (BIAS) { bx = bias[col]; by = bias[col + 1]; }
#pragma unroll
        for (int mt = 0; mt < 2; mt++) {
            int m0 = bm * 128 + wm * 32 + mt * 16 + (lane >> 2);
            if (m0 < M) {
                float2 o = make_float2(acc[mt][nt][0] + bx, acc[mt][nt][1] + by);
                *(float2*)(C + (size_t)m0 * NCOLS + col) = o;
            }
            if (m0 + 8 < M) {
                float2 o = make_float2(acc[mt][nt][2] + bx, acc[mt][nt][3] + by);
                *(float2*)(C + (size_t)(m0 + 8) * NCOLS + col) = o;
            }
        }
    }
}

// ---------------- launch ----------------
extern "C" void kernel_launch(void* const* d_in, const int* in_sizes, int n_in,
                              void* d_out, int out_size) {
    const float* features = (const float*)d_in[0];
    const float* evals    = (const float*)d_in[1];
    const float* W1       = (const float*)d_in[2];
    const float* db1      = (const float*)d_in[3];
    const float* b1       = (const float*)d_in[4];
    const float* g1       = (const float*)d_in[5];
    const float* be1      = (const float*)d_in[6];
    const float* W2       = (const float*)d_in[7];
    const float* b2       = (const float*)d_in[8];
    const float* g2       = (const float*)d_in[9];
    const float* be2      = (const float*)d_in[10];
    const float* Wf       = (const float*)d_in[11];
    const float* bf       = (const float*)d_in[12];
    const int*   erows    = (const int*)d_in[13];
    const int*   ecols    = (const int*)d_in[14];
    const int*   idx      = (const int*)d_in[15];
    float* out = (float*)d_out;
    int Midx = in_sizes[15];

    float *h1, *h2, *stats;
    __nv_bfloat16 *bhi, *blo;
    cudaGetSymbolAddress((void**)&h1, g_h1);
    cudaGetSymbolAddress((void**)&h2, g_h2);
    cudaGetSymbolAddress((void**)&stats, g_stats);
    cudaGetSymbolAddress((void**)&bhi, g_Bhi);
    cudaGetSymbolAddress((void**)&blo, g_Blo);

    int nb1 = (NN + 1023) / 1024;

    // CSR build
    k_zero<<<(NN + 255) / 256, 256>>>();
    k_hist<<<512, 256>>>(erows);
    k_scan1<<<nb1, 1024>>>();
    k_scan2<<<1, 64>>>(nb1);
    k_scan3<<<(NN + 255) / 256, 256>>>();
    k_scatter<<<512, 256>>>(erows, ecols, evals);

    // weight splits (bf16 hi/lo, [N,K] layout)
    k_convW<<<(HD * KD + 255) / 256, 256>>>(W1, bhi, blo, HD);
    k_convW<<<(HD * KD + 255) / 256, 256>>>(W2, bhi + KD * HD, blo + KD * HD, HD);
    k_convW<<<(LD * KD + 255) / 256, 256>>>(Wf, bhi + 2 * KD * HD, blo + 2 * KD * HD, LD);

    dim3 gBig(HD / 128, (NN + 127) / 128);
    int spmmBlocks = (NN * 32 + 255) / 256;

    // layer 1
    k_mmagemm<HD, true, false, false><<<gBig, 256>>>(
        features, bhi, blo, db1, nullptr, nullptr, nullptr, nullptr, h1, NN);
    k_spmm<<<spmmBlocks, 256>>>(h1, b1, h2, stats);

    // layer 2 (BN1+ReLU fused into A-read)
    k_mmagemm<HD, false, false, true><<<gBig, 256>>>(
        h2, bhi + KD * HD, blo + KD * HD, nullptr, nullptr, stats, g1, be1, h1, NN);
    k_spmm<<<spmmBlocks, 256>>>(h1, b2, h2, stats + 2 * HD);

    // head (BN2+ReLU + gather fused)
    dim3 gHead(LD / 128, (Midx + 127) / 128);
    k_mmagemm<LD, true, true, true><<<gHead, 256>>>(
        h2, bhi + 2 * KD * HD, blo + 2 * KD * HD, bf, idx, stats + 2 * HD, g2, be2, out, Midx);
}